// round 15
// baseline (speedup 1.0000x reference)
#include <cuda_runtime.h>
#include <cuda_fp16.h>
#include <cstdint>

#define M_DIM 4096
#define K_DIM 4096
#define N_DIM 11008
#define N_GROUPS 32

#define BM 128
#define BN 128
#define BK 64
#define NSTAGE 6                 // B-only ring now; 6 x 16KB
#define KT_TOTAL (K_DIM / BK)    // 64
#define NTILE_M (M_DIM / BM)     // 32
#define NTILE_N (N_DIM / BN)     // 86

#define B_STG_BYTES (BN * 128)   // 16384: 128 rows x (64 fp16 = 128B), SW128

#define SOFF_FULL  0
#define SOFF_EMPTY 64
#define SOFF_B     1024
#define SMEM_TOTAL (SOFF_B + NSTAGE * B_STG_BYTES)   // 99328 -> 2 CTAs/SM

#define NTHREADS 288   // 8 compute warps + 1 producer warp

#define XBLOCKS (M_DIM * (K_DIM / 8) / 256)   // 8192 (fragment-layout convert)
#define WBLOCKS (N_DIM * (K_DIM / 8) / 256)   // 22016

// Xs: per (m_tile, ktile) 16KB block of PRE-BUILT mma A-fragments:
//   slot ((m16blk*4 + kc)*32 + lane)*16B = {w0,w1,w2,w3} for that lane
// Ws: tiled + SW128-pre-swizzled fp16 (unchanged)
__device__ __half Xs[(size_t)M_DIM * K_DIM];   // 32 MB
__device__ __half Ws[(size_t)N_DIM * K_DIM];   // 90 MB

// ---------------------------------------------------------------------------
#define MBAR_INIT(a, c) \
    asm volatile("mbarrier.init.shared.b64 [%0], %1;" :: "r"(a), "r"(c) : "memory")
#define MBAR_EXPECT_TX(a, b) \
    asm volatile("mbarrier.arrive.expect_tx.shared.b64 _, [%0], %1;" :: "r"(a), "r"(b) : "memory")
#define MBAR_ARRIVE(a) \
    asm volatile("mbarrier.arrive.shared.b64 _, [%0];" :: "r"(a) : "memory")
#define BULK_G2S(dst, src, bytes, mbar) \
    asm volatile("cp.async.bulk.shared::cta.global.mbarrier::complete_tx::bytes [%0], [%1], %2, [%3];" \
                 :: "r"(dst), "l"(src), "r"(bytes), "r"(mbar) : "memory")

#define MBAR_WAIT_PARITY(addr, parity) do {                                      \
    uint32_t _m = (addr); uint32_t _p = (parity); uint32_t _d;                   \
    asm volatile("{\n\t.reg .pred p;\n\t"                                        \
        "mbarrier.try_wait.parity.acquire.cta.shared::cta.b64 p, [%1], %2;\n\t"  \
        "selp.b32 %0, 1, 0, p;\n\t}"                                             \
        : "=r"(_d) : "r"(_m), "r"(_p) : "memory");                               \
    if (!_d) {                                                                   \
        asm volatile("{\n\t.reg .pred P1;\n\t"                                   \
            "WL_%=:\n\t"                                                         \
            "mbarrier.try_wait.parity.acquire.cta.shared::cta.b64 P1, [%0], %1, 0x989680;\n\t" \
            "@P1 bra.uni WD_%=;\n\t"                                             \
            "bra.uni WL_%=;\n\t"                                                 \
            "WD_%=:\n\t}"                                                        \
            :: "r"(_m), "r"(_p) : "memory");                                     \
    }                                                                            \
} while (0)

#define LDMATRIX_X4(r0, r1, r2, r3, a) \
    asm volatile("ldmatrix.sync.aligned.m8n8.x4.shared.b16 {%0,%1,%2,%3}, [%4];" \
                 : "=r"(r0), "=r"(r1), "=r"(r2), "=r"(r3) : "r"(a))

// ---------------------------------------------------------------------------
// Fused prep.
// Blocks [0, XBLOCKS): convert x fp32->fp16 into FRAGMENT layout.
//   One thread builds one lane's 16B fragment for one (mt,kt,b,kc):
//   reads rows r0=g, r1=g+8 at k halves (2t, 2t+1) and (+8): 4x float2,
//   writes one uint4 (perfectly coalesced 512B per warp).
// Blocks [XBLOCKS, ..): dequant W (unchanged SW128-swizzled tile layout).
// ---------------------------------------------------------------------------
__global__ void prep_kernel(const float* __restrict__ x,
                            const int* __restrict__ qw,
                            const float* __restrict__ scales) {
    if (blockIdx.x < XBLOCKS) {
        unsigned idx = blockIdx.x * blockDim.x + threadIdx.x;
        int lane = idx & 31;
        int kc   = (idx >> 5) & 3;
        int b    = (idx >> 7) & 7;
        int kt   = (idx >> 10) & 63;
        int mt   = idx >> 16;
        int g = lane >> 2, t = lane & 3;
        size_t r0 = (size_t)mt * 128 + b * 16 + g;
        size_t r1 = r0 + 8;
        int kbase = kt * 64 + kc * 16 + t * 2;
        const float2* p00 = reinterpret_cast<const float2*>(x + r0 * K_DIM + kbase);
        const float2* p01 = reinterpret_cast<const float2*>(x + r0 * K_DIM + kbase + 8);
        const float2* p10 = reinterpret_cast<const float2*>(x + r1 * K_DIM + kbase);
        const float2* p11 = reinterpret_cast<const float2*>(x + r1 * K_DIM + kbase + 8);
        float2 v00 = *p00, v01 = *p01, v10 = *p10, v11 = *p11;
        union { uint4 u; __half2 h[4]; } o;
        o.h[0] = __floats2half2_rn(v00.x, v00.y);   // w0: row g,   k-low
        o.h[1] = __floats2half2_rn(v10.x, v10.y);   // w1: row g+8, k-low
        o.h[2] = __floats2half2_rn(v01.x, v01.y);   // w2: row g,   k-high
        o.h[3] = __floats2half2_rn(v11.x, v11.y);   // w3: row g+8, k-high
        char* dst = (char*)Xs + (((size_t)mt * KT_TOTAL + kt) << 14)
                  + (((b * 4 + kc) << 9) + (lane << 4));
        *reinterpret_cast<uint4*>(dst) = o.u;
    } else {
        size_t i = (size_t)(blockIdx.x - XBLOCKS) * blockDim.x + threadIdx.x;
        size_t n = i >> 9;
        int k = (int)(i & 511) * 8;
        const int4* src = reinterpret_cast<const int4*>(qw + n * K_DIM + k);
        int4 q0 = src[0], q1 = src[1];
        float s = scales[n * N_GROUPS + (k >> 7)];
        union { uint4 u; __half2 h[4]; } o;
        o.h[0] = __floats2half2_rn((float)(q0.x - 8) * s, (float)(q0.y - 8) * s);
        o.h[1] = __floats2half2_rn((float)(q0.z - 8) * s, (float)(q0.w - 8) * s);
        o.h[2] = __floats2half2_rn((float)(q1.x - 8) * s, (float)(q1.y - 8) * s);
        o.h[3] = __floats2half2_rn((float)(q1.z - 8) * s, (float)(q1.w - 8) * s);
        int nt = (int)(n >> 7), r = (int)(n & 127);
        int stage = k >> 6, c = k & 63;
        uint32_t off = (uint32_t)(r * 128 + c * 2);
        uint32_t sw = off ^ ((off >> 3) & 0x70);
        char* dst = (char*)Ws + (((size_t)nt * KT_TOTAL + stage) << 14) + sw;
        *reinterpret_cast<uint4*>(dst) = o.u;
    }
}

// ---------------------------------------------------------------------------
// HMMA GEMM: A fragments via coalesced LDG.128 from gmem (L1-cached, no smem,
// no barrier), B via 6-stage bulk ring + LDSM (r11-proven sync structure).
// ---------------------------------------------------------------------------
__global__ void __launch_bounds__(NTHREADS, 2) gemm_hmma(float* __restrict__ C) {
    extern __shared__ char smem[];
    uint32_t sb = (uint32_t)__cvta_generic_to_shared(smem);
    const int tid = threadIdx.x;
    const int lane = tid & 31;
    const int warp = tid >> 5;          // 0..7 compute, 8 producer

    const int pid = blockIdx.x;
    const int pid_n = pid / NTILE_M;    // column-major: A (32MB) stays L2-hot
    const int pid_m = pid % NTILE_M;

    if (tid == 0) {
        #pragma unroll
        for (int s = 0; s < NSTAGE; ++s) {
            MBAR_INIT(sb + SOFF_FULL + s * 8, 1);
            MBAR_INIT(sb + SOFF_EMPTY + s * 8, 8);   // one arrive per compute warp
        }
    }
    __syncthreads();

    if (warp == 8) {
        // ---------------- producer warp (B only) ----------------
        if (lane == 0) {
            const char* Bb = (const char*)Ws + ((size_t)pid_n * KT_TOTAL << 14);
            int s = 0, ph = 1;
            for (int kt = 0; kt < KT_TOTAL; ++kt) {
                MBAR_WAIT_PARITY(sb + SOFF_EMPTY + s * 8, (uint32_t)ph);
                uint32_t fb = sb + SOFF_FULL + s * 8;
                MBAR_EXPECT_TX(fb, (uint32_t)B_STG_BYTES);
                BULK_G2S(sb + SOFF_B + s * B_STG_BYTES, Bb + ((size_t)kt << 14),
                         (uint32_t)B_STG_BYTES, fb);
                if (++s == NSTAGE) { s = 0; ph ^= 1; }
            }
        }
        return;
    }

    // ---------------- compute warps: 2 (m) x 4 (n) grid of 64x32 tiles ------
    const int wm = warp >> 2;        // 0..1
    const int wn = warp & 3;         // 0..3

    float acc[4][4][4];
    #pragma unroll
    for (int i = 0; i < 4; i++)
        #pragma unroll
        for (int j = 0; j < 4; j++)
            #pragma unroll
            for (int r = 0; r < 4; r++) acc[i][j][r] = 0.0f;

    const int lrow = (lane & 7) + ((lane >> 3) & 1) * 8;
    const int ksel = (lane >> 4);
    int rB[2];
    #pragma unroll
    for (int j = 0; j < 2; j++) rB[j] = wn * 32 + j * 16 + lrow;

    // A fragment gmem offsets within a (mt,kt) 16KB block:
    //   ((m16blk*4 + kc)*32 + lane) * 16, m16blk = wm*4 + i
    const char* Ablk = (const char*)Xs + ((size_t)pid_m * KT_TOTAL << 14);
    uint32_t aoff[4];
    #pragma unroll
    for (int i = 0; i < 4; i++)
        aoff[i] = (uint32_t)((((wm * 4 + i) * 4) << 9) + (lane << 4));

    int s = 0, ph = 0;
    for (int kt = 0; kt < KT_TOTAL; ++kt) {
        MBAR_WAIT_PARITY(sb + SOFF_FULL + s * 8, (uint32_t)ph);

        const uint32_t Bbase = sb + SOFF_B + s * B_STG_BYTES;
        const char* Akt = Ablk + ((size_t)kt << 14);

        #pragma unroll
        for (int kc = 0; kc < BK / 16; ++kc) {
            const int kseg = kc * 2 + ksel;
            // A fragments: direct coalesced LDG.128, no smem, no barrier
            uint4 av[4];
            #pragma unroll
            for (int i = 0; i < 4; i++)
                av[i] = __ldg(reinterpret_cast<const uint4*>(
                              Akt + aoff[i] + ((uint32_t)kc << 9)));
            uint32_t b[2][4];
            #pragma unroll
            for (int j = 0; j < 2; j++) {
                uint32_t bd = Bbase + rB[j] * 128 + ((kseg ^ (rB[j] & 7)) << 4);
                LDMATRIX_X4(b[j][0], b[j][1], b[j][2], b[j][3], bd);
            }
            // all smem reads of this stage issued once kc==3 B loads done:
            // release the stage to the producer before the final MMA block.
            if (kc == BK / 16 - 1) {
                __syncwarp();
                if (lane == 0) MBAR_ARRIVE(sb + SOFF_EMPTY + s * 8);
            }
            #pragma unroll
            for (int i = 0; i < 4; i++) {
                #pragma unroll
                for (int j = 0; j < 4; j++) {
                    const int jj = j >> 1, lo = j & 1;
                    asm volatile(
                        "mma.sync.aligned.m16n8k16.row.col.f32.f16.f16.f32 "
                        "{%0,%1,%2,%3}, {%4,%5,%6,%7}, {%8,%9}, {%0,%1,%2,%3};\n"
                        : "+f"(acc[i][j][0]), "+f"(acc[i][j][1]),
                          "+f"(acc[i][j][2]), "+f"(acc[i][j][3])
                        : "r"(av[i].x), "r"(av[i].y), "r"(av[i].z), "r"(av[i].w),
                          "r"(b[jj][lo]), "r"(b[jj][2 + lo]));
                }
            }
        }
        if (++s == NSTAGE) { s = 0; ph ^= 1; }
    }

    // epilogue
    #pragma unroll
    for (int i = 0; i < 4; i++) {
        int r0 = pid_m * BM + wm * 64 + i * 16 + (lane >> 2);
        #pragma unroll
        for (int j = 0; j < 4; j++) {
            int cx = pid_n * BN + wn * 32 + j * 8 + (lane & 3) * 2;
            *reinterpret_cast<float2*>(&C[(size_t)r0 * N_DIM + cx]) =
                make_float2(acc[i][j][0], acc[i][j][1]);
            *reinterpret_cast<float2*>(&C[(size_t)(r0 + 8) * N_DIM + cx]) =
                make_float2(acc[i][j][2], acc[i][j][3]);
        }
    }
}

// ---------------------------------------------------------------------------
extern "C" void kernel_launch(void* const* d_in, const int* in_sizes, int n_in,
                              void* d_out, int out_size) {
    const float* x  = (const float*)d_in[0];
    const int*   qw = (const int*)d_in[1];
    const float* sc = (const float*)d_in[2];
    float* out = (float*)d_out;

    prep_kernel<<<XBLOCKS + WBLOCKS, 256>>>(x, qw, sc);

    cudaFuncSetAttribute(gemm_hmma, cudaFuncAttributeMaxDynamicSharedMemorySize, SMEM_TOTAL);
    gemm_hmma<<<NTILE_M * NTILE_N, NTHREADS, SMEM_TOTAL>>>(out);
}

// round 17
// speedup vs baseline: 3.1625x; 3.1625x over previous
#include <cuda_runtime.h>
#include <cuda_fp16.h>
#include <cstdint>

#define M_DIM 4096
#define K_DIM 4096
#define N_DIM 11008
#define N_GROUPS 32

#define BM 128
#define BN 128
#define BK 64
#define NSTAGE 3
#define KT_TOTAL (K_DIM / BK)    // 64
#define NTILE_M (M_DIM / BM)     // 32
#define NTILE_N (N_DIM / BN)     // 86

#define A_STG_BYTES (BM * 128)   // 16384: 128 rows x (64 fp16 = 128B), SW128
#define B_STG_BYTES (BN * 128)   // 16384
#define STAGE_BYTES (A_STG_BYTES + B_STG_BYTES)

#define SOFF_FULL  0
#define SOFF_EMPTY 64
#define SOFF_A     1024
#define SOFF_B     (SOFF_A + NSTAGE * A_STG_BYTES)       // 50176
#define SMEM_TOTAL (SOFF_B + NSTAGE * B_STG_BYTES)       // 99328 -> 2 CTAs/SM

#define NTHREADS 288   // 8 compute warps + 1 producer warp

#define XBLOCKS (M_DIM * (K_DIM / 8) / 256)   // 8192
#define WBLOCKS (N_DIM * (K_DIM / 8) / 256)   // 22016

// Tiled + SW128-pre-swizzled fp16 operands (device globals = sanctioned scratch)
__device__ __half Xs[(size_t)M_DIM * K_DIM];   // 32 MB: [m_tile][k_stage] 16KB blocks
__device__ __half Ws[(size_t)N_DIM * K_DIM];   // 90 MB: [n_tile][k_stage] 16KB blocks

// ---------------------------------------------------------------------------
#define MBAR_INIT(a, c) \
    asm volatile("mbarrier.init.shared.b64 [%0], %1;" :: "r"(a), "r"(c) : "memory")
#define MBAR_EXPECT_TX(a, b) \
    asm volatile("mbarrier.arrive.expect_tx.shared.b64 _, [%0], %1;" :: "r"(a), "r"(b) : "memory")
#define MBAR_ARRIVE(a) \
    asm volatile("mbarrier.arrive.shared.b64 _, [%0];" :: "r"(a) : "memory")
#define BULK_G2S(dst, src, bytes, mbar) \
    asm volatile("cp.async.bulk.shared::cta.global.mbarrier::complete_tx::bytes [%0], [%1], %2, [%3];" \
                 :: "r"(dst), "l"(src), "r"(bytes), "r"(mbar) : "memory")

#define MBAR_WAIT_PARITY(addr, parity) do {                                      \
    uint32_t _m = (addr); uint32_t _p = (parity); uint32_t _d;                   \
    asm volatile("{\n\t.reg .pred p;\n\t"                                        \
        "mbarrier.try_wait.parity.acquire.cta.shared::cta.b64 p, [%1], %2;\n\t"  \
        "selp.b32 %0, 1, 0, p;\n\t}"                                             \
        : "=r"(_d) : "r"(_m), "r"(_p) : "memory");                               \
    if (!_d) {                                                                   \
        asm volatile("{\n\t.reg .pred P1;\n\t"                                   \
            "WL_%=:\n\t"                                                         \
            "mbarrier.try_wait.parity.acquire.cta.shared::cta.b64 P1, [%0], %1, 0x989680;\n\t" \
            "@P1 bra.uni WD_%=;\n\t"                                             \
            "bra.uni WL_%=;\n\t"                                                 \
            "WD_%=:\n\t}"                                                        \
            :: "r"(_m), "r"(_p) : "memory");                                     \
    }                                                                            \
} while (0)

#define LDMATRIX_X4(r0, r1, r2, r3, a) \
    asm volatile("ldmatrix.sync.aligned.m8n8.x4.shared.b16 {%0,%1,%2,%3}, [%4];" \
                 : "=r"(r0), "=r"(r1), "=r"(r2), "=r"(r3) : "r"(a))

// ---------------------------------------------------------------------------
// Fused prep: blocks [0, XBLOCKS) convert x, blocks [XBLOCKS, ..) dequant W.
// ---------------------------------------------------------------------------
__global__ void prep_kernel(const float* __restrict__ x,
                            const int* __restrict__ qw,
                            const float* __restrict__ scales) {
    if (blockIdx.x < XBLOCKS) {
        size_t i = (size_t)blockIdx.x * blockDim.x + threadIdx.x;  // 8 halves/thread
        size_t m = i >> 9;
        int k = (int)(i & 511) * 8;
        const float4* src = reinterpret_cast<const float4*>(x + m * K_DIM + k);
        float4 v0 = src[0], v1 = src[1];
        union { uint4 u; __half2 h[4]; } o;
        o.h[0] = __floats2half2_rn(v0.x, v0.y);
        o.h[1] = __floats2half2_rn(v0.z, v0.w);
        o.h[2] = __floats2half2_rn(v1.x, v1.y);
        o.h[3] = __floats2half2_rn(v1.z, v1.w);
        int mt = (int)(m >> 7), r = (int)(m & 127);
        int stage = k >> 6, c = k & 63;
        uint32_t off = (uint32_t)(r * 128 + c * 2);
        uint32_t sw = off ^ ((off >> 3) & 0x70);
        char* dst = (char*)Xs + (((size_t)mt * KT_TOTAL + stage) << 14) + sw;
        *reinterpret_cast<uint4*>(dst) = o.u;
    } else {
        size_t i = (size_t)(blockIdx.x - XBLOCKS) * blockDim.x + threadIdx.x;
        size_t n = i >> 9;
        int k = (int)(i & 511) * 8;
        const int4* src = reinterpret_cast<const int4*>(qw + n * K_DIM + k);
        int4 q0 = src[0], q1 = src[1];
        float s = scales[n * N_GROUPS + (k >> 7)];
        union { uint4 u; __half2 h[4]; } o;
        o.h[0] = __floats2half2_rn((float)(q0.x - 8) * s, (float)(q0.y - 8) * s);
        o.h[1] = __floats2half2_rn((float)(q0.z - 8) * s, (float)(q0.w - 8) * s);
        o.h[2] = __floats2half2_rn((float)(q1.x - 8) * s, (float)(q1.y - 8) * s);
        o.h[3] = __floats2half2_rn((float)(q1.z - 8) * s, (float)(q1.w - 8) * s);
        int nt = (int)(n >> 7), r = (int)(n & 127);
        int stage = k >> 6, c = k & 63;
        uint32_t off = (uint32_t)(r * 128 + c * 2);
        uint32_t sw = off ^ ((off >> 3) & 0x70);
        char* dst = (char*)Ws + (((size_t)nt * KT_TOTAL + stage) << 14) + sw;
        *reinterpret_cast<uint4*>(dst) = o.u;
    }
}

// ---------------------------------------------------------------------------
// HMMA GEMM: 128x128 tile, 3-stage bulk ring, producer warp, early empty-arrive
// (the proven 928.8us configuration, bitwise-reproduced)
// ---------------------------------------------------------------------------
__global__ void __launch_bounds__(NTHREADS, 2) gemm_hmma(float* __restrict__ C) {
    extern __shared__ char smem[];
    uint32_t sb = (uint32_t)__cvta_generic_to_shared(smem);
    const int tid = threadIdx.x;
    const int lane = tid & 31;
    const int warp = tid >> 5;          // 0..7 compute, 8 producer

    const int pid = blockIdx.x;
    const int pid_n = pid / NTILE_M;    // column-major: A (32MB) stays L2-hot
    const int pid_m = pid % NTILE_M;

    if (tid == 0) {
        #pragma unroll
        for (int s = 0; s < NSTAGE; ++s) {
            MBAR_INIT(sb + SOFF_FULL + s * 8, 1);
            MBAR_INIT(sb + SOFF_EMPTY + s * 8, 8);   // one arrive per compute warp
        }
    }
    __syncthreads();

    if (warp == 8) {
        // ---------------- producer warp ----------------
        if (lane == 0) {
            const char* Ab = (const char*)Xs + ((size_t)pid_m * KT_TOTAL << 14);
            const char* Bb = (const char*)Ws + ((size_t)pid_n * KT_TOTAL << 14);
            int s = 0, ph = 1;
            for (int kt = 0; kt < KT_TOTAL; ++kt) {
                MBAR_WAIT_PARITY(sb + SOFF_EMPTY + s * 8, (uint32_t)ph);
                uint32_t fb = sb + SOFF_FULL + s * 8;
                MBAR_EXPECT_TX(fb, (uint32_t)STAGE_BYTES);
                BULK_G2S(sb + SOFF_A + s * A_STG_BYTES, Ab + ((size_t)kt << 14),
                         (uint32_t)A_STG_BYTES, fb);
                BULK_G2S(sb + SOFF_B + s * B_STG_BYTES, Bb + ((size_t)kt << 14),
                         (uint32_t)B_STG_BYTES, fb);
                if (++s == NSTAGE) { s = 0; ph ^= 1; }
            }
        }
        return;
    }

    // ---------------- compute warps: 2 (m) x 4 (n) grid of 64x32 tiles ------
    const int wm = warp >> 2;        // 0..1
    const int wn = warp & 3;         // 0..3

    float acc[4][4][4];
    #pragma unroll
    for (int i = 0; i < 4; i++)
        #pragma unroll
        for (int j = 0; j < 4; j++)
            #pragma unroll
            for (int r = 0; r < 4; r++) acc[i][j][r] = 0.0f;

    const int lrow = (lane & 7) + ((lane >> 3) & 1) * 8;
    const int ksel = (lane >> 4);
    int rA[4], rB[2];
    #pragma unroll
    for (int i = 0; i < 4; i++) rA[i] = wm * 64 + i * 16 + lrow;
    #pragma unroll
    for (int j = 0; j < 2; j++) rB[j] = wn * 32 + j * 16 + lrow;

    int s = 0, ph = 0;
    for (int kt = 0; kt < KT_TOTAL; ++kt) {
        MBAR_WAIT_PARITY(sb + SOFF_FULL + s * 8, (uint32_t)ph);

        const uint32_t Abase = sb + SOFF_A + s * A_STG_BYTES;
        const uint32_t Bbase = sb + SOFF_B + s * B_STG_BYTES;

        #pragma unroll
        for (int kc = 0; kc < BK / 16; ++kc) {
            const int kseg = kc * 2 + ksel;
            uint32_t a[4][4];
            #pragma unroll
            for (int i = 0; i < 4; i++) {
                uint32_t ad = Abase + rA[i] * 128 + ((kseg ^ (rA[i] & 7)) << 4);
                LDMATRIX_X4(a[i][0], a[i][1], a[i][2], a[i][3], ad);
            }
            uint32_t b[2][4];
            #pragma unroll
            for (int j = 0; j < 2; j++) {
                uint32_t bd = Bbase + rB[j] * 128 + ((kseg ^ (rB[j] & 7)) << 4);
                LDMATRIX_X4(b[j][0], b[j][1], b[j][2], b[j][3], bd);
            }
            // all smem reads of this stage issued once kc==3 loads are done:
            // release the stage to the producer before the final MMA block.
            if (kc == BK / 16 - 1) {
                __syncwarp();
                if (lane == 0) MBAR_ARRIVE(sb + SOFF_EMPTY + s * 8);
            }
            #pragma unroll
            for (int i = 0; i < 4; i++) {
                #pragma unroll
                for (int j = 0; j < 4; j++) {
                    const int jj = j >> 1, lo = j & 1;
                    asm volatile(
                        "mma.sync.aligned.m16n8k16.row.col.f32.f16.f16.f32 "
                        "{%0,%1,%2,%3}, {%4,%5,%6,%7}, {%8,%9}, {%0,%1,%2,%3};\n"
                        : "+f"(acc[i][j][0]), "+f"(acc[i][j][1]),
                          "+f"(acc[i][j][2]), "+f"(acc[i][j][3])
                        : "r"(a[i][0]), "r"(a[i][1]), "r"(a[i][2]), "r"(a[i][3]),
                          "r"(b[jj][lo]), "r"(b[jj][2 + lo]));
                }
            }
        }
        if (++s == NSTAGE) { s = 0; ph ^= 1; }
    }

    // epilogue
    #pragma unroll
    for (int i = 0; i < 4; i++) {
        int r0 = pid_m * BM + wm * 64 + i * 16 + (lane >> 2);
        #pragma unroll
        for (int j = 0; j < 4; j++) {
            int cx = pid_n * BN + wn * 32 + j * 8 + (lane & 3) * 2;
            *reinterpret_cast<float2*>(&C[(size_t)r0 * N_DIM + cx]) =
                make_float2(acc[i][j][0], acc[i][j][1]);
            *reinterpret_cast<float2*>(&C[(size_t)(r0 + 8) * N_DIM + cx]) =
                make_float2(acc[i][j][2], acc[i][j][3]);
        }
    }
}

// ---------------------------------------------------------------------------
extern "C" void kernel_launch(void* const* d_in, const int* in_sizes, int n_in,
                              void* d_out, int out_size) {
    const float* x  = (const float*)d_in[0];
    const int*   qw = (const int*)d_in[1];
    const float* sc = (const float*)d_in[2];
    float* out = (float*)d_out;

    prep_kernel<<<XBLOCKS + WBLOCKS, 256>>>(x, qw, sc);

    cudaFuncSetAttribute(gemm_hmma, cudaFuncAttributeMaxDynamicSharedMemorySize, SMEM_TOTAL);
    gemm_hmma<<<NTILE_M * NTILE_N, NTHREADS, SMEM_TOTAL>>>(out);
}